// round 15
// baseline (speedup 1.0000x reference)
#include <cuda_runtime.h>
#include <cstdint>
#include <math_constants.h>

// OpeningLoss2D: mean((x - grey_opening_2x2(x))^2) over [8,16,512,512] fp32.
// Separable hmin2 -> vmin2 -> hmax2 -> vmax2 (scipy w=2, edge replicate,
// er-index clamps on dilation).
//
// Dual-slice blocks: 512 blocks x 256 threads; each block processes TWO
// adjacent channel slices (A: threads 0-127, B: threads 128-255) over the
// same 64-row band. Slot row layout [A 512 | -inf | B 512 | -inf] (1032 fl).
// cp.async ring: 12 slots (49.5KB), 2-row groups, depth 5; one wait+barrier
// per 4KB. Slot schedule identical to the rel_err-validated R14 kernel:
// row p <-> slot p%12, super-iterations of 6, peeled tail, zero overrun.

#define FULLMASK 0xffffffffu

static const int Hc = 512;
static const int Wc = 512;
static const int TR = 64;
static const int NBLK = 512;           // 64 slice-pairs * 8 row-tiles
static const int ROWP = 1032;          // slot stride (floats); 4128 B, 16B-mult
static const int RING = 12;            // 49.5 KB

__device__ float g_partials[NBLK];
__device__ unsigned int g_count = 0;

__device__ __forceinline__ void cp_async16(uint32_t saddr, const float* gaddr) {
    asm volatile("cp.async.cg.shared.global [%0], [%1], 16;\n"
                 :: "r"(saddr), "l"(gaddr));
}
__device__ __forceinline__ void cp_commit() {
    asm volatile("cp.async.commit_group;\n" ::: "memory");
}
template <int N>
__device__ __forceinline__ void cp_wait() {
    asm volatile("cp.async.wait_group %0;\n" :: "n"(N) : "memory");
}

__global__ void __launch_bounds__(256, 4)
opening_kernel(const float* __restrict__ X, float* __restrict__ out) {
    __shared__ float ring[RING][ROWP];    // A [0..511], pad 512, B [516..1027], pad 1028
    __shared__ float wsum[8];
    __shared__ bool amLast;

    const int t      = threadIdx.x;       // 0..255
    const int lane   = t & 31;
    const int warpId = t >> 5;
    const int tile   = blockIdx.x;        // 0..511
    const int pairI  = tile >> 3;         // 0..63
    const int r0     = (tile & 7) * TR;
    const int half   = (t >> 7);          // 0 = slice A, 1 = slice B
    const float* S   = X + (size_t)(pairI * 2 + half) * (Hc * Wc);
    const int c0l    = (t & 127) << 2;    // local column 0..508
    const int hb     = half ? 516 : 0;    // smem half base
    const bool isL0  = (lane == 0);
    const bool isL31 = (lane == 31);
    const int lcol   = hb + max(c0l - 1, 0);   // left clamp at slice col 0
    const int rcol   = hb + c0l + 4;           // last thread -> -inf sentinel

    if (t < RING) { ring[t][512] = -CUDART_INF_F; ring[t][1028] = -CUDART_INF_F; }

    const uint32_t sring =
        (uint32_t)__cvta_generic_to_shared(&ring[0][0]) +
        (uint32_t)((hb + c0l) * 4);

    #define LOADROW(sl)                                                       \
        const float* _row = &ring[(sl)][0];                                   \
        float4 _q = *reinterpret_cast<const float4*>(_row + hb + c0l);        \
        float _L = __shfl_up_sync(FULLMASK, _q.w, 1);                         \
        float _R = __shfl_down_sync(FULLMASK, _q.x, 1);                       \
        if (isL0)  _L = _row[lcol];                                           \
        if (isL31) _R = _row[rcol];                                           \
        float _h0 = fminf(_L,  _q.x), _h1 = fminf(_q.x, _q.y);                \
        float _h2 = fminf(_q.y, _q.z), _h3 = fminf(_q.z, _q.w);               \
        float _h4 = fminf(_q.w, _R);

    #define FULLROW(sl) do {                                                  \
        LOADROW(sl)                                                            \
        float _e0 = fminf(hp0,_h0), _e1 = fminf(hp1,_h1), _e2 = fminf(hp2,_h2);\
        float _e3 = fminf(hp3,_h3), _e4 = fminf(hp4,_h4);                      \
        float _M0 = fmaxf(_e0,_e1), _M1 = fmaxf(_e1,_e2);                      \
        float _M2 = fmaxf(_e2,_e3), _M3 = fmaxf(_e3,_e4);                      \
        float _s0 = fmaxf(Mp0,_M0), _s1 = fmaxf(Mp1,_M1);                      \
        float _s2 = fmaxf(Mp2,_M2), _s3 = fmaxf(Mp3,_M3);                      \
        float _d0 = xp0 - _s0, _d1 = xp1 - _s1;                                \
        float _d2 = xp2 - _s2, _d3 = xp3 - _s3;                                \
        acc0 = fmaf(_d0,_d0,acc0); acc1 = fmaf(_d1,_d1,acc1);                  \
        acc0 = fmaf(_d2,_d2,acc0); acc1 = fmaf(_d3,_d3,acc1);                  \
        hp0=_h0; hp1=_h1; hp2=_h2; hp3=_h3; hp4=_h4;                           \
        Mp0=_M0; Mp1=_M1; Mp2=_M2; Mp3=_M3;                                    \
        xp0=_q.x; xp1=_q.y; xp2=_q.z; xp3=_q.w;                                \
    } while (0)

    float hp0, hp1, hp2, hp3, hp4;
    float Mp0, Mp1, Mp2, Mp3;
    float xp0, xp1, xp2, xp3;
    float acc0 = 0.f, acc1 = 0.f;

    // ---- prologue: rows 0..9 -> slots 0..9 (5 groups). Row p = x row
    // clamp(r0-1+p); only p=0 can clamp low; p<=9 never clamps high.
    #define ISSUEP(p) cp_async16(sring + (uint32_t)((p) * (ROWP * 4)),        \
                                 S + (size_t)max(r0 - 1 + (p), 0) * Wc + c0l)
    ISSUEP(0); ISSUEP(1); cp_commit();
    ISSUEP(2); ISSUEP(3); cp_commit();
    ISSUEP(4); ISSUEP(5); cp_commit();
    ISSUEP(6); ISSUEP(7); cp_commit();
    ISSUEP(8); ISSUEP(9); cp_commit();

    // ---- step 0 (rows 0,1): issue rows 10,11 -> slots 10,11
    cp_wait<4>();
    __syncthreads();
    ISSUEP(10); ISSUEP(11); cp_commit();
    #undef ISSUEP
    {   LOADROW(0)
        hp0=_h0; hp1=_h1; hp2=_h2; hp3=_h3; hp4=_h4;
    }
    {   LOADROW(1)
        float _e0 = fminf(hp0,_h0), _e1 = fminf(hp1,_h1), _e2 = fminf(hp2,_h2);
        float _e3 = fminf(hp3,_h3), _e4 = fminf(hp4,_h4);
        Mp0 = fmaxf(_e0,_e1); Mp1 = fmaxf(_e1,_e2);
        Mp2 = fmaxf(_e2,_e3); Mp3 = fmaxf(_e3,_e4);
        hp0=_h0; hp1=_h1; hp2=_h2; hp3=_h3; hp4=_h4;
        xp0=_q.x; xp1=_q.y; xp2=_q.z; xp3=_q.w;
    }

    // ---- hot loop: steps 1..24 in 4 super-iterations of 6. Step s reads
    // rows 2s,2s+1 (slots (2s)%12), issues rows 2s+10,2s+11 into slots read
    // at step s-1 (barrier-ordered). Issued x rows r0+11..r0+58 <= 506 for
    // every tile: no clamps. Before step s: s+5 groups committed; wait<4>
    // completes group s -> rows <= 2s+1 resident.
    #define HOT(KOFF, RS, WS) do {                                            \
        cp_wait<4>();                                                         \
        __syncthreads();                                                      \
        cp_async16(sring + (uint32_t)((WS)     * (ROWP * 4)),                 \
                   gq + (size_t)(KOFF) * Wc);                                 \
        cp_async16(sring + (uint32_t)(((WS)+1) * (ROWP * 4)),                 \
                   gq + (size_t)((KOFF)+1) * Wc);                             \
        cp_commit();                                                          \
        FULLROW(RS);                                                          \
        FULLROW((RS)+1);                                                      \
    } while (0)

    const float* gq = S + (size_t)(r0 + 11) * Wc + c0l;   // pipeline row 12
    #pragma unroll 1
    for (int i = 0; i < 4; ++i) {
        HOT(0, 2, 0);     // s = 6i+1
        HOT(2, 4, 2);     // s = 6i+2
        HOT(4, 6, 4);     // s = 6i+3
        HOT(6, 8, 6);     // s = 6i+4
        HOT(8, 10, 8);    // s = 6i+5
        HOT(10, 0, 10);   // s = 6i+6
        gq += 12 * Wc;
    }
    #undef HOT

    // ---- peeled steps 25..27: issue last rows 60..65 (clamped high for the
    // bottom tile: r0=448 -> x row up to 512 -> min to 511).
    #define PEELI(p0, WS) do {                                                \
        int _g0 = min(r0 - 1 + (p0), Hc - 1);                                 \
        int _g1 = min(r0 + (p0), Hc - 1);                                     \
        cp_async16(sring + (uint32_t)((WS)     * (ROWP * 4)),                 \
                   S + (size_t)_g0 * Wc + c0l);                               \
        cp_async16(sring + (uint32_t)(((WS)+1) * (ROWP * 4)),                 \
                   S + (size_t)_g1 * Wc + c0l);                               \
        cp_commit();                                                          \
    } while (0)

    // s=25: rows 50,51 (slots 2,3); issue rows 60,61 -> slots 0,1
    cp_wait<4>(); __syncthreads(); PEELI(60, 0); FULLROW(2); FULLROW(3);
    // s=26: rows 52,53 (slots 4,5); issue rows 62,63 -> slots 2,3
    cp_wait<4>(); __syncthreads(); PEELI(62, 2); FULLROW(4); FULLROW(5);
    // s=27: rows 54,55 (slots 6,7); issue rows 64,65 -> slots 4,5
    cp_wait<4>(); __syncthreads(); PEELI(64, 4); FULLROW(6); FULLROW(7);
    #undef PEELI
    // All 33 groups committed (rows 0..65, zero overrun). Countdown:
    cp_wait<4>(); __syncthreads(); FULLROW(8);  FULLROW(9);   // rows 56,57
    cp_wait<3>(); __syncthreads(); FULLROW(10); FULLROW(11);  // rows 58,59
    cp_wait<2>(); __syncthreads(); FULLROW(0);  FULLROW(1);   // rows 60,61
    cp_wait<1>(); __syncthreads(); FULLROW(2);  FULLROW(3);   // rows 62,63
    cp_wait<0>(); __syncthreads();
    FULLROW(4);                                                // row 64
    if (r0 + TR >= Hc) {
        // er row 512 doesn't exist: smooth(511) = hM(511) = Mp
        float _d0 = xp0 - Mp0, _d1 = xp1 - Mp1;
        float _d2 = xp2 - Mp2, _d3 = xp3 - Mp3;
        acc0 = fmaf(_d0,_d0,acc0); acc1 = fmaf(_d1,_d1,acc1);
        acc0 = fmaf(_d2,_d2,acc0); acc1 = fmaf(_d3,_d3,acc1);
    } else {
        FULLROW(5);                                            // row 65
    }
    #undef LOADROW
    #undef FULLROW

    float acc = acc0 + acc1;
    #pragma unroll
    for (int off = 16; off; off >>= 1)
        acc += __shfl_down_sync(FULLMASK, acc, off);
    if (lane == 0) wsum[warpId] = acc;
    __syncthreads();
    if (t == 0) {
        float s = 0.f;
        #pragma unroll
        for (int i = 0; i < 8; ++i) s += wsum[i];
        g_partials[blockIdx.x] = s;
        __threadfence();
        unsigned int old = atomicAdd(&g_count, 1u);
        amLast = (old == (unsigned)(NBLK - 1));
    }
    __syncthreads();

    if (amLast) {
        __shared__ float sh[256];
        float s = 0.f;
        for (int i = t; i < NBLK; i += 256) s += g_partials[i];
        sh[t] = s;
        __syncthreads();
        #pragma unroll
        for (int off = 128; off; off >>= 1) {
            if (t < off) sh[t] += sh[t + off];
            __syncthreads();
        }
        if (t == 0) {
            out[0] = sh[0] * (1.0f / 33554432.0f);  // mean over 8*16*512*512
            g_count = 0;                            // deterministic replays
        }
    }
}

extern "C" void kernel_launch(void* const* d_in, const int* in_sizes, int n_in,
                              void* d_out, int out_size) {
    const float* X = (const float*)d_in[0];
    opening_kernel<<<NBLK, 256>>>(X, (float*)d_out);
}

// round 16
// speedup vs baseline: 1.1152x; 1.1152x over previous
#include <cuda_runtime.h>
#include <cstdint>
#include <math_constants.h>

// OpeningLoss2D: mean((x - grey_opening_2x2(x))^2) over [8,16,512,512] fp32.
// Separable hmin2 -> vmin2 -> hmax2 -> vmax2 (scipy w=2, edge replicate,
// er-index clamps on dilation).
//
// TMA-bulk producer: 1024 blocks x 128 threads, 512x64 tiles. Ring of 12
// tight 512-float row slots (24KB) filled by cp.async.bulk (2KB whole-row
// copies, 2 rows/group, 5 groups in flight) with mbarrier complete_tx.
// One elected thread issues; warp 0 acquires via try_wait.parity; a block
// barrier propagates visibility. Slot schedule identical to the
// rel_err-validated R14 kernel: row p <-> slot p%12, 6-step super-iterations,
// peeled tail, zero overrun. Right-edge dilation clamp = -inf select on the
// last thread (ring rows are tight, no sentinel column).

#define FULLMASK 0xffffffffu

static const int Hc = 512;
static const int Wc = 512;
static const int TR = 64;
static const int NBLK = 1024;          // 128 slices * 8 row-tiles
static const int RING = 12;            // row slots = 6 groups of 2 rows

__device__ float g_partials[NBLK];
__device__ unsigned int g_count = 0;

__device__ __forceinline__ void mbar_init(uint32_t addr, uint32_t cnt) {
    asm volatile("mbarrier.init.shared.b64 [%0], %1;" :: "r"(addr), "r"(cnt) : "memory");
}
__device__ __forceinline__ void mbar_expect(uint32_t addr, uint32_t bytes) {
    asm volatile("mbarrier.arrive.expect_tx.shared.b64 _, [%0], %1;"
                 :: "r"(addr), "r"(bytes) : "memory");
}
__device__ __forceinline__ void mbar_wait(uint32_t addr, uint32_t parity) {
    asm volatile(
        "{\n\t"
        ".reg .pred P;\n\t"
        "WL_%=:\n\t"
        "mbarrier.try_wait.parity.acquire.cta.shared::cta.b64 P, [%0], %1, 0x989680;\n\t"
        "@P bra WD_%=;\n\t"
        "bra WL_%=;\n\t"
        "WD_%=:\n\t"
        "}"
        :: "r"(addr), "r"(parity) : "memory");
}
__device__ __forceinline__ void bulk2k(uint32_t dst, const float* src, uint32_t mba) {
    asm volatile(
        "cp.async.bulk.shared::cluster.global.mbarrier::complete_tx::bytes "
        "[%0], [%1], 2048, [%2];"
        :: "r"(dst), "l"(src), "r"(mba) : "memory");
}

__global__ void __launch_bounds__(128, 9)
opening_kernel(const float* __restrict__ X, float* __restrict__ out) {
    __shared__ __align__(16) float ring[RING * Wc + 16];  // +16 fl pad (OOB-read guard)
    __shared__ __align__(8) unsigned long long mbar[6];
    __shared__ float wsum[4];
    __shared__ bool amLast;

    const int t      = threadIdx.x;       // 0..127
    const int lane   = t & 31;
    const int warpId = t >> 5;
    const int tile   = blockIdx.x;        // 0..1023
    const int slice  = tile >> 3;         // 0..127
    const int r0     = (tile & 7) * TR;
    const float* S   = X + (size_t)slice * (Hc * Wc);
    const int c0     = t << 2;            // first owned column (0..508)
    const bool isL0  = (lane == 0);
    const bool isL31 = (lane == 31);
    const bool lastT = (t == 127);
    const int lcol   = max(c0 - 1, 0);    // left clamp (t=0 -> col 0)

    const uint32_t sring = (uint32_t)__cvta_generic_to_shared(&ring[0]);
    const uint32_t mb    = (uint32_t)__cvta_generic_to_shared(&mbar[0]);

    if (t == 0) {
        #pragma unroll
        for (int b = 0; b < 6; ++b) mbar_init(mb + b * 8, 1);
    }
    __syncthreads();

    #define LOADROW(sl)                                                       \
        const float* _row = &ring[(sl) * Wc];                                 \
        float4 _q = *reinterpret_cast<const float4*>(_row + c0);              \
        float _L = __shfl_up_sync(FULLMASK, _q.w, 1);                         \
        float _R = __shfl_down_sync(FULLMASK, _q.x, 1);                       \
        if (isL0)  _L = _row[lcol];                                           \
        if (isL31) _R = lastT ? -CUDART_INF_F : _row[c0 + 4];                 \
        float _h0 = fminf(_L,  _q.x), _h1 = fminf(_q.x, _q.y);                \
        float _h2 = fminf(_q.y, _q.z), _h3 = fminf(_q.z, _q.w);               \
        float _h4 = fminf(_q.w, _R);

    #define FULLROW(sl) do {                                                  \
        LOADROW(sl)                                                            \
        float _e0 = fminf(hp0,_h0), _e1 = fminf(hp1,_h1), _e2 = fminf(hp2,_h2);\
        float _e3 = fminf(hp3,_h3), _e4 = fminf(hp4,_h4);                      \
        float _M0 = fmaxf(_e0,_e1), _M1 = fmaxf(_e1,_e2);                      \
        float _M2 = fmaxf(_e2,_e3), _M3 = fmaxf(_e3,_e4);                      \
        float _s0 = fmaxf(Mp0,_M0), _s1 = fmaxf(Mp1,_M1);                      \
        float _s2 = fmaxf(Mp2,_M2), _s3 = fmaxf(Mp3,_M3);                      \
        float _d0 = xp0 - _s0, _d1 = xp1 - _s1;                                \
        float _d2 = xp2 - _s2, _d3 = xp3 - _s3;                                \
        acc0 = fmaf(_d0,_d0,acc0); acc1 = fmaf(_d1,_d1,acc1);                  \
        acc0 = fmaf(_d2,_d2,acc0); acc1 = fmaf(_d3,_d3,acc1);                  \
        hp0=_h0; hp1=_h1; hp2=_h2; hp3=_h3; hp4=_h4;                           \
        Mp0=_M0; Mp1=_M1; Mp2=_M2; Mp3=_M3;                                    \
        xp0=_q.x; xp1=_q.y; xp2=_q.z; xp3=_q.w;                                \
    } while (0)

    // Clamped issue: group -> barrier bi, dst slots s0,s0+1, pipeline rows p0,p0+1
    // (x rows clamp(r0-1+p0), clamp(r0+p0)).
    #define CISSUE(bi, s0, p0) do { if (t == 0) {                              \
        uint32_t _m = mb + (bi) * 8;                                           \
        mbar_expect(_m, 4096);                                                 \
        bulk2k(sring + (uint32_t)((s0) * 2048),                                \
               S + (size_t)min(max(r0 - 1 + (p0), 0), Hc - 1) * Wc, _m);       \
        bulk2k(sring + (uint32_t)(((s0) + 1) * 2048),                          \
               S + (size_t)min(r0 + (p0), Hc - 1) * Wc, _m);                   \
    } } while (0)

    // Hot issue: clamp-free, running pointer gsrc (advanced by all threads).
    #define HISSUE(bi, s0) do { if (t == 0) {                                  \
        uint32_t _m = mb + (bi) * 8;                                           \
        mbar_expect(_m, 4096);                                                 \
        bulk2k(sring + (uint32_t)((s0) * 2048), gsrc, _m);                     \
        bulk2k(sring + (uint32_t)(((s0) + 1) * 2048), gsrc + Wc, _m);          \
    } gsrc += 2 * Wc; } while (0)

    // step: warp0 acquires full[bi] at parity par; barrier propagates; issue; 2 rows
    #define STEP(bi, par, ISSUE_STMT, RS0, RS1) do {                           \
        if (t < 32) mbar_wait(mb + (bi) * 8, (uint32_t)(par));                 \
        __syncthreads();                                                       \
        ISSUE_STMT;                                                            \
        FULLROW(RS0); FULLROW(RS1);                                            \
    } while (0)

    float hp0, hp1, hp2, hp3, hp4;
    float Mp0, Mp1, Mp2, Mp3;
    float xp0, xp1, xp2, xp3;
    float acc0 = 0.f, acc1 = 0.f;

    // ---- prologue: groups 0..4 (rows 0..9 -> slots 0..9, barriers 0..4)
    CISSUE(0, 0, 0); CISSUE(1, 2, 2); CISSUE(2, 4, 4);
    CISSUE(3, 6, 6); CISSUE(4, 8, 8);

    // ---- step 0 (group 0: rows 0,1; peeled): issue group 5 (slots 10,11)
    if (t < 32) mbar_wait(mb + 0 * 8, 0u);
    __syncthreads();
    CISSUE(5, 10, 10);
    {   LOADROW(0)
        hp0=_h0; hp1=_h1; hp2=_h2; hp3=_h3; hp4=_h4;
    }
    {   LOADROW(Wc ? 1 : 1)   // slot 1
        float _e0 = fminf(hp0,_h0), _e1 = fminf(hp1,_h1), _e2 = fminf(hp2,_h2);
        float _e3 = fminf(hp3,_h3), _e4 = fminf(hp4,_h4);
        Mp0 = fmaxf(_e0,_e1); Mp1 = fmaxf(_e1,_e2);
        Mp2 = fmaxf(_e2,_e3); Mp3 = fmaxf(_e3,_e4);
        hp0=_h0; hp1=_h1; hp2=_h2; hp3=_h3; hp4=_h4;
        xp0=_q.x; xp1=_q.y; xp2=_q.z; xp3=_q.w;
    }

    // ---- hot loop: steps 1..24 in 4 super-iterations of 6. Step s waits
    // group s (barrier s%6, parity (s/6)&1: first 5 steps parity i&1, 6th
    // parity (i+1)&1), issues group s+5 into the slots read at step s-1
    // (barrier-ordered). Issued x rows r0+11..r0+58 <= 506: no clamps.
    const float* gsrc = S + (size_t)(r0 + 11) * Wc;
    #pragma unroll 1
    for (int i = 0; i < 4; ++i) {
        const int p = i & 1;
        STEP(1, p,     HISSUE(0, 0),  2, 3);    // s=6i+1: rows 12i+2,3
        STEP(2, p,     HISSUE(1, 2),  4, 5);    // s=6i+2
        STEP(3, p,     HISSUE(2, 4),  6, 7);    // s=6i+3
        STEP(4, p,     HISSUE(3, 6),  8, 9);    // s=6i+4
        STEP(5, p,     HISSUE(4, 8), 10, 11);   // s=6i+5
        STEP(0, p ^ 1, HISSUE(5, 10), 0, 1);    // s=6i+6: rows 12i+12,13
    }

    // ---- tail: steps 25..32 (groups 25..32; parities: 25..29 -> 0, 30..32 -> 1)
    // Issues end at step 27 (group 32 = rows 64,65). Zero overrun.
    STEP(1, 0, CISSUE(0, 0, 60), 2, 3);    // s=25: rows 50,51; issue rows 60,61
    STEP(2, 0, CISSUE(1, 2, 62), 4, 5);    // s=26: rows 52,53; issue rows 62,63
    STEP(3, 0, CISSUE(2, 4, 64), 6, 7);    // s=27: rows 54,55; issue rows 64,65
    STEP(4, 0, ,  8, 9);                   // s=28: rows 56,57
    STEP(5, 0, , 10, 11);                  // s=29: rows 58,59
    STEP(0, 1, ,  0, 1);                   // s=30: rows 60,61
    STEP(1, 1, ,  2, 3);                   // s=31: rows 62,63
    // s=32: rows 64,65 (slots 4,5); bottom boundary
    if (t < 32) mbar_wait(mb + 2 * 8, 1u);
    __syncthreads();
    FULLROW(4);
    if (r0 + TR >= Hc) {
        // er row 512 doesn't exist: smooth(511) = hM(511) = Mp
        float _d0 = xp0 - Mp0, _d1 = xp1 - Mp1;
        float _d2 = xp2 - Mp2, _d3 = xp3 - Mp3;
        acc0 = fmaf(_d0,_d0,acc0); acc1 = fmaf(_d1,_d1,acc1);
        acc0 = fmaf(_d2,_d2,acc0); acc1 = fmaf(_d3,_d3,acc1);
    } else {
        FULLROW(5);
    }
    #undef STEP
    #undef HISSUE
    #undef CISSUE
    #undef LOADROW
    #undef FULLROW

    float acc = acc0 + acc1;
    #pragma unroll
    for (int off = 16; off; off >>= 1)
        acc += __shfl_down_sync(FULLMASK, acc, off);
    if (lane == 0) wsum[warpId] = acc;
    __syncthreads();
    if (t == 0) {
        float s = wsum[0] + wsum[1] + wsum[2] + wsum[3];
        g_partials[blockIdx.x] = s;
        __threadfence();
        unsigned int old = atomicAdd(&g_count, 1u);
        amLast = (old == (unsigned)(NBLK - 1));
    }
    __syncthreads();

    if (amLast) {
        __shared__ float sh[128];
        float s = 0.f;
        for (int i = t; i < NBLK; i += 128) s += g_partials[i];
        sh[t] = s;
        __syncthreads();
        #pragma unroll
        for (int off = 64; off; off >>= 1) {
            if (t < off) sh[t] += sh[t + off];
            __syncthreads();
        }
        if (t == 0) {
            out[0] = sh[0] * (1.0f / 33554432.0f);  // mean over 8*16*512*512
            g_count = 0;                            // deterministic replays
        }
    }
}

extern "C" void kernel_launch(void* const* d_in, const int* in_sizes, int n_in,
                              void* d_out, int out_size) {
    const float* X = (const float*)d_in[0];
    opening_kernel<<<NBLK, 128>>>(X, (float*)d_out);
}